// round 1
// baseline (speedup 1.0000x reference)
#include <cuda_runtime.h>
#include <math.h>

// Problem dims (fixed)
#define BB   2
#define LL   1024
#define HH   2048
#define DD   4096      // d = H*E
#define SS   16
#define RR   128
#define TT   2048      // B*L tokens
#define XDBL_N 160     // R + 2S

// ---------------- scratch (static device globals; no allocation) ----------
__device__ float g_xz  [(size_t)TT * 2 * DD];   // x @ W_in           (2048 x 8192)
__device__ float g_xc  [(size_t)TT * DD];       // conv+silu          (2048 x 4096)
__device__ float g_xdbl[(size_t)TT * XDBL_N];   // xc @ W_x           (2048 x 160)
__device__ float g_dt  [(size_t)TT * DD];       // softplus(dt_in@W_dt+b)
__device__ float g_y   [(size_t)TT * DD];       // scan out, then gated mix (in place)

__device__ __forceinline__ float silu_f(float x) {
    return x / (1.0f + __expf(-x));
}
__device__ __forceinline__ float softplus_f(float x) {
    // logaddexp(x, 0) = max(x,0) + log1p(exp(-|x|))
    return fmaxf(x, 0.0f) + log1pf(__expf(-fabsf(x)));
}

// ---------------- generic tiled fp32 GEMM --------------------------------
// C[M,N] = A[M,K(lda)] * B[K,N]; all row-major; exact tiling (no bounds checks:
// every call below divides evenly).
// EPI: 0 = plain store, 1 = +bias then softplus
template<int BM, int BN, int BK, int TM, int TN, int EPI>
__global__ __launch_bounds__((BM/TM)*(BN/TN))
void sgemm_kernel(const float* __restrict__ A, const float* __restrict__ B,
                  float* __restrict__ C, int M, int N, int K, int lda,
                  const float* __restrict__ bias)
{
    constexpr int THREADS = (BM/TM)*(BN/TN);
    __shared__ float As[BK][BM];
    __shared__ float Bs[BK][BN];

    const int tid  = threadIdx.x;
    const int brow = blockIdx.y * BM;
    const int bcol = blockIdx.x * BN;
    const int tcol = (tid % (BN/TN)) * TN;
    const int trow = (tid / (BN/TN)) * TM;

    float acc[TM][TN];
    #pragma unroll
    for (int i = 0; i < TM; i++)
        #pragma unroll
        for (int j = 0; j < TN; j++) acc[i][j] = 0.0f;

    for (int k0 = 0; k0 < K; k0 += BK) {
        constexpr int A4 = BM*BK/4;
        #pragma unroll
        for (int i = tid; i < A4; i += THREADS) {
            int r = i / (BK/4), c = i % (BK/4);
            float4 v = *(const float4*)(A + (size_t)(brow + r)*lda + k0 + c*4);
            As[c*4+0][r] = v.x; As[c*4+1][r] = v.y;
            As[c*4+2][r] = v.z; As[c*4+3][r] = v.w;
        }
        constexpr int B4 = BK*BN/4;
        #pragma unroll
        for (int i = tid; i < B4; i += THREADS) {
            int r = i / (BN/4), c = i % (BN/4);
            *(float4*)(&Bs[r][c*4]) =
                *(const float4*)(B + (size_t)(k0 + r)*N + bcol + c*4);
        }
        __syncthreads();

        #pragma unroll
        for (int kk = 0; kk < BK; kk++) {
            float a[TM], b[TN];
            #pragma unroll
            for (int i = 0; i < TM; i++) a[i] = As[kk][trow + i];
            #pragma unroll
            for (int j = 0; j < TN; j++) b[j] = Bs[kk][tcol + j];
            #pragma unroll
            for (int i = 0; i < TM; i++)
                #pragma unroll
                for (int j = 0; j < TN; j++)
                    acc[i][j] = fmaf(a[i], b[j], acc[i][j]);
        }
        __syncthreads();
    }

    #pragma unroll
    for (int i = 0; i < TM; i++) {
        #pragma unroll
        for (int j = 0; j < TN; j++) {
            float v = acc[i][j];
            int col = bcol + tcol + j;
            if (EPI == 1) { v += bias[col]; v = softplus_f(v); }
            C[(size_t)(brow + trow + i)*N + col] = v;
        }
    }
}

// ---------------- depthwise conv3 (pad 1) + bias + SiLU -------------------
__global__ __launch_bounds__(256)
void conv_silu_kernel(const float* __restrict__ xz, const float* __restrict__ w,
                      const float* __restrict__ bias, float* __restrict__ xc)
{
    int i = blockIdx.x * blockDim.x + threadIdx.x;
    const int NW = TT * (DD/4);
    if (i >= NW) return;
    int c4 = i % (DD/4);
    int t  = i / (DD/4);
    int l  = t & (LL - 1);
    int c  = c4 * 4;

    const float* p = xz + (size_t)t * (2*DD) + c;
    float4 x0 = *(const float4*)p;
    float4 xm = (l > 0)      ? *(const float4*)(p - 2*DD) : make_float4(0,0,0,0);
    float4 xp = (l < LL - 1) ? *(const float4*)(p + 2*DD) : make_float4(0,0,0,0);

    float xmv[4] = {xm.x, xm.y, xm.z, xm.w};
    float x0v[4] = {x0.x, x0.y, x0.z, x0.w};
    float xpv[4] = {xp.x, xp.y, xp.z, xp.w};
    float out[4];
    #pragma unroll
    for (int j = 0; j < 4; j++) {
        int cc = c + j;
        float v = xmv[j]*w[cc*3+0] + x0v[j]*w[cc*3+1] + xpv[j]*w[cc*3+2] + bias[cc];
        out[j] = silu_f(v);
    }
    float4 o = make_float4(out[0], out[1], out[2], out[3]);
    *(float4*)(xc + (size_t)t*DD + c) = o;
}

// ---------------- selective scan -----------------------------------------
// One thread per (b, channel). State h[16] in registers.
// dA_s = exp(dt * A_s), A_s = -exp(A_log[c,s]) ~= -(s+1). Compute p = exp(-dt)
// once per step, build p^(s+1) via binary powers, correct with per-channel
// residual eps_s = (s+1) - exp(A_log[c,s]):   dA_s ~= p^(s+1) * (1 + eps_s*dt).
__global__ __launch_bounds__(128)
void scan_kernel(const float* __restrict__ xc, const float* __restrict__ dt,
                 const float* __restrict__ xdbl, const float* __restrict__ A_log,
                 float* __restrict__ y)
{
    int c = blockIdx.x * 128 + threadIdx.x;   // channel, 0..DD-1
    int b = blockIdx.y;

    float eps[SS];
    #pragma unroll
    for (int s = 0; s < SS; s++)
        eps[s] = (float)(s + 1) - expf(A_log[(size_t)c*SS + s]);

    float h[SS];
    #pragma unroll
    for (int s = 0; s < SS; s++) h[s] = 0.0f;

    const size_t base = (size_t)b * LL * DD + c;
    const size_t xb   = (size_t)b * LL * XDBL_N + RR;

    float u   = xc[base];
    float dtv = dt[base];

    for (int l = 0; l < LL; l++) {
        // prefetch next token's u / dt
        float un = 0.0f, dtn = 0.0f;
        if (l + 1 < LL) {
            un  = xc[base + (size_t)(l+1)*DD];
            dtn = dt[base + (size_t)(l+1)*DD];
        }
        const float* xd = xdbl + xb + (size_t)l * XDBL_N;
        float4 Bv0 = *(const float4*)(xd + 0);
        float4 Bv1 = *(const float4*)(xd + 4);
        float4 Bv2 = *(const float4*)(xd + 8);
        float4 Bv3 = *(const float4*)(xd + 12);
        float4 Cv0 = *(const float4*)(xd + 16);
        float4 Cv1 = *(const float4*)(xd + 20);
        float4 Cv2 = *(const float4*)(xd + 24);
        float4 Cv3 = *(const float4*)(xd + 28);
        float Bv[SS] = {Bv0.x,Bv0.y,Bv0.z,Bv0.w, Bv1.x,Bv1.y,Bv1.z,Bv1.w,
                        Bv2.x,Bv2.y,Bv2.z,Bv2.w, Bv3.x,Bv3.y,Bv3.z,Bv3.w};
        float Cv[SS] = {Cv0.x,Cv0.y,Cv0.z,Cv0.w, Cv1.x,Cv1.y,Cv1.z,Cv1.w,
                        Cv2.x,Cv2.y,Cv2.z,Cv2.w, Cv3.x,Cv3.y,Cv3.z,Cv3.w};

        float p1  = __expf(-dtv);
        float p2  = p1*p1;
        float p4  = p2*p2;
        float p8  = p4*p4;
        float p16 = p8*p8;
        float du  = dtv * u;

        float y0 = 0.f, y1 = 0.f, y2 = 0.f, y3 = 0.f;
        #pragma unroll
        for (int s = 0; s < SS; s++) {
            const int e = s + 1;
            float pw = 1.0f;
            if (e & 1)  pw *= p1;
            if (e & 2)  pw *= p2;
            if (e & 4)  pw *= p4;
            if (e & 8)  pw *= p8;
            if (e & 16) pw *= p16;
            float dA = pw * fmaf(eps[s], dtv, 1.0f);
            h[s] = fmaf(dA, h[s], du * Bv[s]);
            float t2 = h[s] * Cv[s];
            if      ((s & 3) == 0) y0 += t2;
            else if ((s & 3) == 1) y1 += t2;
            else if ((s & 3) == 2) y2 += t2;
            else                   y3 += t2;
        }
        y[base + (size_t)l*DD] = (y0 + y1) + (y2 + y3);
        u = un; dtv = dtn;
    }
}

// ---------------- gated mix: y = (y_scan + xc*D) * silu(z) ----------------
__global__ __launch_bounds__(256)
void final_mix_kernel(const float* __restrict__ xz, const float* __restrict__ xc,
                      const float* __restrict__ D, float* __restrict__ y)
{
    int i = blockIdx.x * blockDim.x + threadIdx.x;
    const int NW = TT * (DD/4);
    if (i >= NW) return;
    int c4 = i % (DD/4);
    int t  = i / (DD/4);
    int c  = c4 * 4;

    float4 ys  = *(float4*)      (y  + (size_t)t*DD + c);
    float4 xcv = *(const float4*)(xc + (size_t)t*DD + c);
    float4 Dv  = *(const float4*)(D + c);
    float4 zv  = *(const float4*)(xz + (size_t)t*(2*DD) + DD + c);

    float4 o;
    o.x = fmaf(xcv.x, Dv.x, ys.x) * silu_f(zv.x);
    o.y = fmaf(xcv.y, Dv.y, ys.y) * silu_f(zv.y);
    o.z = fmaf(xcv.z, Dv.z, ys.z) * silu_f(zv.z);
    o.w = fmaf(xcv.w, Dv.w, ys.w) * silu_f(zv.w);
    *(float4*)(y + (size_t)t*DD + c) = o;
}

// ---------------- launch ---------------------------------------------------
extern "C" void kernel_launch(void* const* d_in, const int* in_sizes, int n_in,
                              void* d_out, int out_size)
{
    const float* x      = (const float*)d_in[0];
    const float* W_in   = (const float*)d_in[1];
    const float* conv_w = (const float*)d_in[2];
    const float* conv_b = (const float*)d_in[3];
    const float* W_x    = (const float*)d_in[4];
    const float* W_dt   = (const float*)d_in[5];
    const float* b_dt   = (const float*)d_in[6];
    const float* A_log  = (const float*)d_in[7];
    const float* D      = (const float*)d_in[8];
    const float* W_out  = (const float*)d_in[9];
    float* out = (float*)d_out;

    float *xz, *xc, *xdbl, *dtb, *y;
    cudaGetSymbolAddress((void**)&xz,   g_xz);
    cudaGetSymbolAddress((void**)&xc,   g_xc);
    cudaGetSymbolAddress((void**)&xdbl, g_xdbl);
    cudaGetSymbolAddress((void**)&dtb,  g_dt);
    cudaGetSymbolAddress((void**)&y,    g_y);

    // 1) xz = x @ W_in   (2048 x 8192 x K=2048)
    sgemm_kernel<128,128,16,8,8,0><<<dim3(2*DD/128, TT/128), 256>>>(
        x, W_in, xz, TT, 2*DD, HH, HH, nullptr);

    // 2) depthwise conv3 + bias + silu -> xc
    conv_silu_kernel<<<(TT*(DD/4) + 255)/256, 256>>>(xz, conv_w, conv_b, xc);

    // 3) x_dbl = xc @ W_x   (2048 x 160 x K=4096)
    sgemm_kernel<128,32,16,8,4,0><<<dim3(XDBL_N/32, TT/128), 128>>>(
        xc, W_x, xdbl, TT, XDBL_N, DD, DD, nullptr);

    // 4) dt = softplus(x_dbl[:, :R] @ W_dt + b_dt)   (2048 x 4096 x K=128)
    sgemm_kernel<128,128,16,8,8,1><<<dim3(DD/128, TT/128), 256>>>(
        xdbl, W_dt, dtb, TT, DD, RR, XDBL_N, b_dt);

    // 5) selective scan -> y
    scan_kernel<<<dim3(DD/128, BB), 128>>>(xc, dtb, xdbl, A_log, y);

    // 6) y = (y + xc*D) * silu(z)  (in place)
    final_mix_kernel<<<(TT*(DD/4) + 255)/256, 256>>>(xz, xc, D, y);

    // 7) out = y @ W_out   (2048 x 2048 x K=4096)
    sgemm_kernel<128,128,16,8,8,0><<<dim3(HH/128, TT/128), 256>>>(
        y, W_out, out, TT, HH, DD, DD, nullptr);
}

// round 6
// speedup vs baseline: 1.7908x; 1.7908x over previous
#include <cuda_runtime.h>
#include <cuda_bf16.h>
#include <math.h>
#include <stdint.h>

// Problem dims (fixed)
#define BBATCH 2
#define LL   1024
#define HH   2048
#define DD   4096      // d = H*E
#define SSTATE 16
#define RR   128
#define TT   2048      // B*L tokens
#define XDBL_N 160     // R + 2S

// ---------------- scratch (static device globals; no allocation) ----------
__device__ float g_xz  [(size_t)TT * 2 * DD];
__device__ float g_xc  [(size_t)TT * DD];
__device__ float g_xdbl[(size_t)TT * XDBL_N];
__device__ float g_dt  [(size_t)TT * DD];
__device__ float g_y   [(size_t)TT * DD];

// bf16 split operands (hi/lo)
__device__ __nv_bfloat16 g_xh [(size_t)TT * HH];
__device__ __nv_bfloat16 g_xl [(size_t)TT * HH];
__device__ __nv_bfloat16 g_wih[(size_t)2 * DD * HH];   // W_in^T  [8192][2048]
__device__ __nv_bfloat16 g_wil[(size_t)2 * DD * HH];
__device__ __nv_bfloat16 g_woh[(size_t)HH * DD];       // W_out^T [2048][4096]
__device__ __nv_bfloat16 g_wol[(size_t)HH * DD];
__device__ __nv_bfloat16 g_wdh[(size_t)DD * RR];       // W_dt^T  [4096][128]
__device__ __nv_bfloat16 g_wdl[(size_t)DD * RR];
__device__ __nv_bfloat16 g_dih[(size_t)TT * RR];       // dt_in   [2048][128]
__device__ __nv_bfloat16 g_dil[(size_t)TT * RR];
__device__ __nv_bfloat16 g_yh [(size_t)TT * DD];
__device__ __nv_bfloat16 g_yl [(size_t)TT * DD];

// ---------------- small helpers ------------------------------------------
__device__ __forceinline__ float silu_f(float x) { return x / (1.0f + __expf(-x)); }
__device__ __forceinline__ float softplus_f(float x) {
    return fmaxf(x, 0.0f) + log1pf(__expf(-fabsf(x)));
}
__device__ __forceinline__ uint32_t smem_u32(const void* p) {
    uint32_t a;
    asm("{ .reg .u64 t; cvta.to.shared.u64 t, %1; cvt.u32.u64 %0, t; }" : "=r"(a) : "l"(p));
    return a;
}
__device__ __forceinline__ unsigned short bf16_bits(__nv_bfloat16 h) {
    unsigned short u; *(__nv_bfloat16*)&u = h; return u;
}
__device__ __forceinline__ void split1(float v, unsigned short& h, unsigned short& l) {
    __nv_bfloat16 hb = __float2bfloat16(v);
    __nv_bfloat16 lb = __float2bfloat16(v - __bfloat162float(hb));
    h = bf16_bits(hb); l = bf16_bits(lb);
}
__device__ __forceinline__ void cp_async16(uint32_t dst, const void* src) {
    asm volatile("cp.async.cg.shared.global [%0], [%1], 16;" :: "r"(dst), "l"(src));
}
__device__ __forceinline__ void ldsm_x4(uint32_t addr, uint32_t& r0, uint32_t& r1,
                                        uint32_t& r2, uint32_t& r3) {
    asm volatile("ldmatrix.sync.aligned.m8n8.x4.shared.b16 {%0,%1,%2,%3}, [%4];"
                 : "=r"(r0), "=r"(r1), "=r"(r2), "=r"(r3) : "r"(addr));
}
__device__ __forceinline__ void mma_bf16(float* c, uint32_t a0, uint32_t a1,
                                         uint32_t a2, uint32_t a3,
                                         uint32_t b0, uint32_t b1) {
    asm volatile(
        "mma.sync.aligned.m16n8k16.row.col.f32.bf16.bf16.f32 "
        "{%0,%1,%2,%3}, {%4,%5,%6,%7}, {%8,%9}, {%0,%1,%2,%3};"
        : "+f"(c[0]), "+f"(c[1]), "+f"(c[2]), "+f"(c[3])
        : "r"(a0), "r"(a1), "r"(a2), "r"(a3), "r"(b0), "r"(b1));
}

// ---------------- mma.sync split-bf16 GEMM --------------------------------
// C[M,N] = Af32 @ Bf32^T. A ~ Ah+Al ([M][K] bf16), B rows are Bh/Bl [N][K].
// Tile 128x128, BK=64, 2-stage cp.async pipeline, 256 threads.
// EPI: 0 plain, 1 = +bias then softplus
#define MG_TILE  16384          // 128 rows x 128B (64 bf16)
#define MG_STAGE (4 * MG_TILE)  // Ah, Al, Bh, Bl
#define MG_SMEM  (2 * MG_STAGE + 1024)

template<int EPI>
__global__ __launch_bounds__(256)
void mma_gemm_kernel(const __nv_bfloat16* __restrict__ Ah, const __nv_bfloat16* __restrict__ Al,
                     const __nv_bfloat16* __restrict__ Bh, const __nv_bfloat16* __restrict__ Bl,
                     float* __restrict__ C, int M, int N, int K,
                     const float* __restrict__ bias)
{
    extern __shared__ char smem_raw[];
    const uint32_t sb = (smem_u32(smem_raw) + 1023u) & ~1023u;

    const int tid  = threadIdx.x;
    const int lane = tid & 31;
    const int wid  = tid >> 5;
    const int wm   = wid & 1;        // 0..1 -> 64-row slab
    const int wn   = wid >> 1;       // 0..3 -> 32-col slab
    const int bm = blockIdx.y * 128;
    const int bn = blockIdx.x * 128;

    // cp.async chunk offsets: per tile, 1024 chunks of 16B; 4 per thread.
    uint32_t swoff[4]; size_t goff[4];
    #pragma unroll
    for (int i = 0; i < 4; i++) {
        int c = i * 256 + tid;
        int row = c >> 3, kb = c & 7;
        uint32_t o = (uint32_t)(row * 128 + kb * 16);
        swoff[i] = o ^ ((o >> 3) & 0x70);
        goff[i]  = (size_t)row * (size_t)K * 2 + (size_t)kb * 16;
    }
    const char* gsrc[4] = {
        (const char*)(Ah + (size_t)bm * K), (const char*)(Al + (size_t)bm * K),
        (const char*)(Bh + (size_t)bn * K), (const char*)(Bl + (size_t)bn * K) };

    float acc[4][4][4];
    #pragma unroll
    for (int mi = 0; mi < 4; mi++)
        #pragma unroll
        for (int ni = 0; ni < 4; ni++)
            #pragma unroll
            for (int r = 0; r < 4; r++) acc[mi][ni][r] = 0.0f;

    const int NK = K >> 6;

    // -- stage loader --
    auto load_stage = [&](int kblk, int s) {
        uint32_t base = sb + (uint32_t)s * MG_STAGE;
        size_t kadd = (size_t)kblk * 128;   // 64 bf16 = 128 bytes
        #pragma unroll
        for (int o = 0; o < 4; o++) {
            uint32_t tdst = base + o * MG_TILE;
            const char* g = gsrc[o] + kadd;
            #pragma unroll
            for (int i = 0; i < 4; i++) cp_async16(tdst + swoff[i], g + goff[i]);
        }
        asm volatile("cp.async.commit_group;" ::: "memory");
    };

    load_stage(0, 0);

    for (int kblk = 0; kblk < NK; kblk++) {
        int s = kblk & 1;
        if (kblk + 1 < NK) {
            load_stage(kblk + 1, 1 - s);
            asm volatile("cp.async.wait_group 1;" ::: "memory");
        } else {
            asm volatile("cp.async.wait_group 0;" ::: "memory");
        }
        __syncthreads();

        uint32_t base = sb + (uint32_t)s * MG_STAGE;
        #pragma unroll
        for (int p = 0; p < 3; p++) {
            uint32_t tA = base + (p == 2 ? MG_TILE : 0);
            uint32_t tB = base + 2 * MG_TILE + (p == 1 ? MG_TILE : 0);
            #pragma unroll
            for (int k16 = 0; k16 < 4; k16++) {
                const int kb = k16 * 32;    // byte offset of this k16 chunk
                // B frags: 4 n8 frags (8 regs) via two x4 ldmatrix
                uint32_t b[8];
                #pragma unroll
                for (int nj = 0; nj < 2; nj++) {
                    int nrow = wn * 32 + nj * 16 + (lane & 7) + ((lane >> 4) << 3);
                    int ko   = kb + (((lane >> 3) & 1) << 4);
                    uint32_t o = (uint32_t)(nrow * 128 + ko);
                    o ^= ((o >> 3) & 0x70);
                    ldsm_x4(tB + o, b[nj*4+0], b[nj*4+1], b[nj*4+2], b[nj*4+3]);
                }
                #pragma unroll
                for (int mi = 0; mi < 4; mi++) {
                    int mrow = wm * 64 + mi * 16 + (lane & 15);
                    int ko   = kb + ((lane >> 4) << 4);
                    uint32_t o = (uint32_t)(mrow * 128 + ko);
                    o ^= ((o >> 3) & 0x70);
                    uint32_t a0, a1, a2, a3;
                    ldsm_x4(tA + o, a0, a1, a2, a3);
                    #pragma unroll
                    for (int ni = 0; ni < 4; ni++)
                        mma_bf16(acc[mi][ni], a0, a1, a2, a3, b[ni*2], b[ni*2+1]);
                }
            }
        }
        __syncthreads();
    }

    // -- epilogue --
    #pragma unroll
    for (int mi = 0; mi < 4; mi++) {
        #pragma unroll
        for (int ni = 0; ni < 4; ni++) {
            int row = bm + wm * 64 + mi * 16 + (lane >> 2);
            int col = bn + wn * 32 + ni * 8 + (lane & 3) * 2;
            float2 v0 = make_float2(acc[mi][ni][0], acc[mi][ni][1]);
            float2 v1 = make_float2(acc[mi][ni][2], acc[mi][ni][3]);
            if (EPI == 1) {
                float b0 = __ldg(bias + col), b1 = __ldg(bias + col + 1);
                v0.x = softplus_f(v0.x + b0); v0.y = softplus_f(v0.y + b1);
                v1.x = softplus_f(v1.x + b0); v1.y = softplus_f(v1.y + b1);
            }
            *(float2*)(C + (size_t)row * N + col)       = v0;
            *(float2*)(C + (size_t)(row + 8) * N + col) = v1;
        }
    }
}

// ---------------- prep kernels --------------------------------------------
__global__ __launch_bounds__(256)
void split_kernel(const float* __restrict__ in, __nv_bfloat16* __restrict__ hi,
                  __nv_bfloat16* __restrict__ lo, int n4)
{
    int i = blockIdx.x * 256 + threadIdx.x;
    if (i >= n4) return;
    float4 v = ((const float4*)in)[i];
    ushort4 h, l;
    split1(v.x, h.x, l.x); split1(v.y, h.y, l.y);
    split1(v.z, h.z, l.z); split1(v.w, h.w, l.w);
    ((ushort4*)hi)[i] = h;
    ((ushort4*)lo)[i] = l;
}

// in: [R][C] fp32 -> outH/L: [C][R] bf16  (R, C multiples of 32)
__global__ __launch_bounds__(256)
void trsplit_kernel(const float* __restrict__ in, __nv_bfloat16* __restrict__ oh,
                    __nv_bfloat16* __restrict__ ol, int R, int C)
{
    __shared__ float t[32][33];
    int c0 = blockIdx.x * 32, r0 = blockIdx.y * 32;
    int tx = threadIdx.x, ty = threadIdx.y;
    #pragma unroll
    for (int j = 0; j < 4; j++)
        t[ty + 8 * j][tx] = in[(size_t)(r0 + ty + 8 * j) * C + c0 + tx];
    __syncthreads();
    #pragma unroll
    for (int j = 0; j < 4; j++) {
        float v = t[tx][ty + 8 * j];
        unsigned short h, l; split1(v, h, l);
        size_t o = (size_t)(c0 + ty + 8 * j) * R + r0 + tx;
        *(unsigned short*)(oh + o) = h;
        *(unsigned short*)(ol + o) = l;
    }
}

// dt_in split: xdbl[:, 0:128] (lda=160) -> [2048][128] bf16 pairs
__global__ __launch_bounds__(256)
void split_dtin_kernel(const float* __restrict__ xdbl, __nv_bfloat16* __restrict__ oh,
                       __nv_bfloat16* __restrict__ ol)
{
    int i = blockIdx.x * 256 + threadIdx.x;
    if (i >= TT * (RR / 4)) return;
    int row = i >> 5, c4 = i & 31;
    float4 v = *(const float4*)(xdbl + (size_t)row * XDBL_N + c4 * 4);
    ushort4 h, l;
    split1(v.x, h.x, l.x); split1(v.y, h.y, l.y);
    split1(v.z, h.z, l.z); split1(v.w, h.w, l.w);
    size_t o = ((size_t)row * RR + c4 * 4) >> 2;
    ((ushort4*)oh)[o] = h;
    ((ushort4*)ol)[o] = l;
}

// ---------------- fp32 SIMT GEMM (GEMM3 only) -----------------------------
template<int BM, int BN, int BK, int TM, int TN>
__global__ __launch_bounds__((BM/TM)*(BN/TN))
void sgemm_kernel(const float* __restrict__ A, const float* __restrict__ B,
                  float* __restrict__ C, int M, int N, int K, int lda)
{
    constexpr int THREADS = (BM/TM)*(BN/TN);
    __shared__ float As[BK][BM];
    __shared__ float Bs[BK][BN];

    const int tid  = threadIdx.x;
    const int brow = blockIdx.y * BM;
    const int bcol = blockIdx.x * BN;
    const int tcol = (tid % (BN/TN)) * TN;
    const int trow = (tid / (BN/TN)) * TM;

    float acc[TM][TN];
    #pragma unroll
    for (int i = 0; i < TM; i++)
        #pragma unroll
        for (int j = 0; j < TN; j++) acc[i][j] = 0.0f;

    for (int k0 = 0; k0 < K; k0 += BK) {
        constexpr int A4 = BM*BK/4;
        #pragma unroll
        for (int i = tid; i < A4; i += THREADS) {
            int r = i / (BK/4), c = i % (BK/4);
            float4 v = *(const float4*)(A + (size_t)(brow + r)*lda + k0 + c*4);
            As[c*4+0][r] = v.x; As[c*4+1][r] = v.y;
            As[c*4+2][r] = v.z; As[c*4+3][r] = v.w;
        }
        constexpr int B4 = BK*BN/4;
        #pragma unroll
        for (int i = tid; i < B4; i += THREADS) {
            int r = i / (BN/4), c = i % (BN/4);
            *(float4*)(&Bs[r][c*4]) =
                *(const float4*)(B + (size_t)(k0 + r)*N + bcol + c*4);
        }
        __syncthreads();

        #pragma unroll
        for (int kk = 0; kk < BK; kk++) {
            float a[TM], b[TN];
            #pragma unroll
            for (int i = 0; i < TM; i++) a[i] = As[kk][trow + i];
            #pragma unroll
            for (int j = 0; j < TN; j++) b[j] = Bs[kk][tcol + j];
            #pragma unroll
            for (int i = 0; i < TM; i++)
                #pragma unroll
                for (int j = 0; j < TN; j++)
                    acc[i][j] = fmaf(a[i], b[j], acc[i][j]);
        }
        __syncthreads();
    }

    #pragma unroll
    for (int i = 0; i < TM; i++)
        #pragma unroll
        for (int j = 0; j < TN; j++)
            C[(size_t)(brow + trow + i)*N + bcol + tcol + j] = acc[i][j];
}

// ---------------- depthwise conv3 (pad 1) + bias + SiLU -------------------
__global__ __launch_bounds__(256)
void conv_silu_kernel(const float* __restrict__ xz, const float* __restrict__ w,
                      const float* __restrict__ bias, float* __restrict__ xc)
{
    int i = blockIdx.x * blockDim.x + threadIdx.x;
    const int NW = TT * (DD/4);
    if (i >= NW) return;
    int c4 = i % (DD/4);
    int t  = i / (DD/4);
    int l  = t & (LL - 1);
    int c  = c4 * 4;

    const float* p = xz + (size_t)t * (2*DD) + c;
    float4 x0 = *(const float4*)p;
    float4 xm = (l > 0)      ? *(const float4*)(p - 2*DD) : make_float4(0,0,0,0);
    float4 xp = (l < LL - 1) ? *(const float4*)(p + 2*DD) : make_float4(0,0,0,0);

    float xmv[4] = {xm.x, xm.y, xm.z, xm.w};
    float x0v[4] = {x0.x, x0.y, x0.z, x0.w};
    float xpv[4] = {xp.x, xp.y, xp.z, xp.w};
    float out[4];
    #pragma unroll
    for (int j = 0; j < 4; j++) {
        int cc = c + j;
        float v = xmv[j]*w[cc*3+0] + x0v[j]*w[cc*3+1] + xpv[j]*w[cc*3+2] + bias[cc];
        out[j] = silu_f(v);
    }
    *(float4*)(xc + (size_t)t*DD + c) = make_float4(out[0], out[1], out[2], out[3]);
}

// ---------------- selective scan ------------------------------------------
__global__ __launch_bounds__(128)
void scan_kernel(const float* __restrict__ xc, const float* __restrict__ dt,
                 const float* __restrict__ xdbl, const float* __restrict__ A_log,
                 float* __restrict__ y)
{
    int c = blockIdx.x * 128 + threadIdx.x;
    int b = blockIdx.y;

    float eps[SSTATE];
    #pragma unroll
    for (int s = 0; s < SSTATE; s++)
        eps[s] = (float)(s + 1) - expf(A_log[(size_t)c*SSTATE + s]);

    float h[SSTATE];
    #pragma unroll
    for (int s = 0; s < SSTATE; s++) h[s] = 0.0f;

    const size_t base = (size_t)b * LL * DD + c;
    const size_t xb   = (size_t)b * LL * XDBL_N + RR;

    float u   = xc[base];
    float dtv = dt[base];

    for (int l = 0; l < LL; l++) {
        float un = 0.0f, dtn = 0.0f;
        if (l + 1 < LL) {
            un  = xc[base + (size_t)(l+1)*DD];
            dtn = dt[base + (size_t)(l+1)*DD];
        }
        const float* xd = xdbl + xb + (size_t)l * XDBL_N;
        float4 Bv0 = *(const float4*)(xd + 0);
        float4 Bv1 = *(const float4*)(xd + 4);
        float4 Bv2 = *(const float4*)(xd + 8);
        float4 Bv3 = *(const float4*)(xd + 12);
        float4 Cv0 = *(const float4*)(xd + 16);
        float4 Cv1 = *(const float4*)(xd + 20);
        float4 Cv2 = *(const float4*)(xd + 24);
        float4 Cv3 = *(const float4*)(xd + 28);
        float Bv[SSTATE] = {Bv0.x,Bv0.y,Bv0.z,Bv0.w, Bv1.x,Bv1.y,Bv1.z,Bv1.w,
                            Bv2.x,Bv2.y,Bv2.z,Bv2.w, Bv3.x,Bv3.y,Bv3.z,Bv3.w};
        float Cv[SSTATE] = {Cv0.x,Cv0.y,Cv0.z,Cv0.w, Cv1.x,Cv1.y,Cv1.z,Cv1.w,
                            Cv2.x,Cv2.y,Cv2.z,Cv2.w, Cv3.x,Cv3.y,Cv3.z,Cv3.w};

        float p1  = __expf(-dtv);
        float p2  = p1*p1;
        float p4  = p2*p2;
        float p8  = p4*p4;
        float p16 = p8*p8;
        float du  = dtv * u;

        float y0 = 0.f, y1 = 0.f, y2 = 0.f, y3 = 0.f;
        #pragma unroll
        for (int s = 0; s < SSTATE; s++) {
            const int e = s + 1;
            float pw = 1.0f;
            if (e & 1)  pw *= p1;
            if (e & 2)  pw *= p2;
            if (e & 4)  pw *= p4;
            if (e & 8)  pw *= p8;
            if (e & 16) pw *= p16;
            float dA = pw * fmaf(eps[s], dtv, 1.0f);
            h[s] = fmaf(dA, h[s], du * Bv[s]);
            float t2 = h[s] * Cv[s];
            if      ((s & 3) == 0) y0 += t2;
            else if ((s & 3) == 1) y1 += t2;
            else if ((s & 3) == 2) y2 += t2;
            else                   y3 += t2;
        }
        y[base + (size_t)l*DD] = (y0 + y1) + (y2 + y3);
        u = un; dtv = dtn;
    }
}

// ---------------- gated mix + split: yh/yl = split((y + xc*D) * silu(z)) ---
__global__ __launch_bounds__(256)
void final_mix_kernel(const float* __restrict__ xz, const float* __restrict__ xc,
                      const float* __restrict__ D, const float* __restrict__ y,
                      __nv_bfloat16* __restrict__ yh, __nv_bfloat16* __restrict__ yl)
{
    int i = blockIdx.x * blockDim.x + threadIdx.x;
    const int NW = TT * (DD/4);
    if (i >= NW) return;
    int c4 = i % (DD/4);
    int t  = i / (DD/4);
    int c  = c4 * 4;

    float4 ys  = *(const float4*)(y  + (size_t)t*DD + c);
    float4 xcv = *(const float4*)(xc + (size_t)t*DD + c);
    float4 Dv  = *(const float4*)(D + c);
    float4 zv  = *(const float4*)(xz + (size_t)t*(2*DD) + DD + c);

    float o0 = fmaf(xcv.x, Dv.x, ys.x) * silu_f(zv.x);
    float o1 = fmaf(xcv.y, Dv.y, ys.y) * silu_f(zv.y);
    float o2 = fmaf(xcv.z, Dv.z, ys.z) * silu_f(zv.z);
    float o3 = fmaf(xcv.w, Dv.w, ys.w) * silu_f(zv.w);

    ushort4 h, l;
    split1(o0, h.x, l.x); split1(o1, h.y, l.y);
    split1(o2, h.z, l.z); split1(o3, h.w, l.w);
    size_t o = ((size_t)t*DD + c) >> 2;
    ((ushort4*)yh)[o] = h;
    ((ushort4*)yl)[o] = l;
}

// ---------------- launch ---------------------------------------------------
extern "C" void kernel_launch(void* const* d_in, const int* in_sizes, int n_in,
                              void* d_out, int out_size)
{
    const float* x      = (const float*)d_in[0];
    const float* W_in   = (const float*)d_in[1];
    const float* conv_w = (const float*)d_in[2];
    const float* conv_b = (const float*)d_in[3];
    const float* W_x    = (const float*)d_in[4];
    const float* W_dt   = (const float*)d_in[5];
    const float* b_dt   = (const float*)d_in[6];
    const float* A_log  = (const float*)d_in[7];
    const float* D      = (const float*)d_in[8];
    const float* W_out  = (const float*)d_in[9];
    float* out = (float*)d_out;

    float *xz, *xc, *xdbl, *dtb, *y;
    __nv_bfloat16 *xh, *xl, *wih, *wil, *woh, *wol, *wdh, *wdl, *dih, *dil, *yh, *yl;
    cudaGetSymbolAddress((void**)&xz,   g_xz);
    cudaGetSymbolAddress((void**)&xc,   g_xc);
    cudaGetSymbolAddress((void**)&xdbl, g_xdbl);
    cudaGetSymbolAddress((void**)&dtb,  g_dt);
    cudaGetSymbolAddress((void**)&y,    g_y);
    cudaGetSymbolAddress((void**)&xh,  g_xh);  cudaGetSymbolAddress((void**)&xl,  g_xl);
    cudaGetSymbolAddress((void**)&wih, g_wih); cudaGetSymbolAddress((void**)&wil, g_wil);
    cudaGetSymbolAddress((void**)&woh, g_woh); cudaGetSymbolAddress((void**)&wol, g_wol);
    cudaGetSymbolAddress((void**)&wdh, g_wdh); cudaGetSymbolAddress((void**)&wdl, g_wdl);
    cudaGetSymbolAddress((void**)&dih, g_dih); cudaGetSymbolAddress((void**)&dil, g_dil);
    cudaGetSymbolAddress((void**)&yh,  g_yh);  cudaGetSymbolAddress((void**)&yl,  g_yl);

    cudaFuncSetAttribute(mma_gemm_kernel<0>, cudaFuncAttributeMaxDynamicSharedMemorySize, MG_SMEM);
    cudaFuncSetAttribute(mma_gemm_kernel<1>, cudaFuncAttributeMaxDynamicSharedMemorySize, MG_SMEM);

    // prep: split activations / transpose+split weights
    split_kernel<<<(TT*HH/4 + 255)/256, 256>>>(x, xh, xl, TT*HH/4);
    trsplit_kernel<<<dim3(2*DD/32, HH/32), dim3(32,8)>>>(W_in,  wih, wil, HH,  2*DD);
    trsplit_kernel<<<dim3(HH/32,  DD/32),  dim3(32,8)>>>(W_out, woh, wol, DD,  HH);
    trsplit_kernel<<<dim3(DD/32,  RR/32),  dim3(32,8)>>>(W_dt,  wdh, wdl, RR,  DD);

    // 1) xz = x @ W_in    (2048 x 8192, K=2048)  mma.sync bf16-split
    mma_gemm_kernel<0><<<dim3(2*DD/128, TT/128), 256, MG_SMEM>>>(
        xh, xl, wih, wil, xz, TT, 2*DD, HH, nullptr);

    // 2) depthwise conv3 + bias + silu -> xc
    conv_silu_kernel<<<(TT*(DD/4) + 255)/256, 256>>>(xz, conv_w, conv_b, xc);

    // 3) x_dbl = xc @ W_x   (2048 x 160, K=4096)  fp32 SIMT
    sgemm_kernel<128,32,16,8,4><<<dim3(XDBL_N/32, TT/128), 128>>>(
        xc, W_x, xdbl, TT, XDBL_N, DD, DD);

    // 4) dt = softplus(x_dbl[:, :R] @ W_dt + b_dt)  mma.sync bf16-split
    split_dtin_kernel<<<(TT*(RR/4) + 255)/256, 256>>>(xdbl, dih, dil);
    mma_gemm_kernel<1><<<dim3(DD/128, TT/128), 256, MG_SMEM>>>(
        dih, dil, wdh, wdl, dtb, TT, DD, RR, b_dt);

    // 5) selective scan -> y
    scan_kernel<<<dim3(DD/128, BBATCH), 128>>>(xc, dtb, xdbl, A_log, y);

    // 6) yh/yl = split((y + xc*D) * silu(z))
    final_mix_kernel<<<(TT*(DD/4) + 255)/256, 256>>>(xz, xc, D, y, yh, yl);

    // 7) out = y @ W_out   (2048 x 2048, K=4096)  mma.sync bf16-split
    mma_gemm_kernel<0><<<dim3(HH/128, TT/128), 256, MG_SMEM>>>(
        yh, yl, woh, wol, out, TT, HH, DD, nullptr);
}

// round 9
// speedup vs baseline: 2.4548x; 1.3708x over previous
#include <cuda_runtime.h>
#include <cuda_bf16.h>
#include <math.h>
#include <stdint.h>

// Problem dims (fixed)
#define BBATCH 2
#define LL   1024
#define HH   2048
#define DD   4096      // d = H*E
#define SSTATE 16
#define RR   128
#define TT   2048      // B*L tokens
#define XDBL_N 160     // R + 2S
#define XPAD 256       // padded x_dbl width
#define NSPLITK 8

// ---------------- scratch (static device globals; no allocation) ----------
__device__ float g_xz  [(size_t)TT * 2 * DD];
__device__ float g_xc  [(size_t)TT * DD];
__device__ float g_xdbl[(size_t)TT * XPAD];                 // padded
__device__ float g_xpart[(size_t)NSPLITK * TT * XPAD];      // split-K partials
__device__ float g_dt  [(size_t)TT * DD];
__device__ float g_y   [(size_t)TT * DD];

// bf16 split operands (hi/lo)
__device__ __nv_bfloat16 g_xh [(size_t)TT * HH];
__device__ __nv_bfloat16 g_xl [(size_t)TT * HH];
__device__ __nv_bfloat16 g_wih[(size_t)2 * DD * HH];   // W_in^T  [8192][2048]
__device__ __nv_bfloat16 g_wil[(size_t)2 * DD * HH];
__device__ __nv_bfloat16 g_woh[(size_t)HH * DD];       // W_out^T [2048][4096]
__device__ __nv_bfloat16 g_wol[(size_t)HH * DD];
__device__ __nv_bfloat16 g_wdh[(size_t)DD * RR];       // W_dt^T  [4096][128]
__device__ __nv_bfloat16 g_wdl[(size_t)DD * RR];
__device__ __nv_bfloat16 g_wxh[(size_t)XPAD * DD];     // W_x^T   [256(pad)][4096], rows 160+ stay 0
__device__ __nv_bfloat16 g_wxl[(size_t)XPAD * DD];
__device__ __nv_bfloat16 g_xch[(size_t)TT * DD];       // split of xc
__device__ __nv_bfloat16 g_xcl[(size_t)TT * DD];
__device__ __nv_bfloat16 g_dih[(size_t)TT * RR];       // dt_in   [2048][128]
__device__ __nv_bfloat16 g_dil[(size_t)TT * RR];
__device__ __nv_bfloat16 g_yh [(size_t)TT * DD];
__device__ __nv_bfloat16 g_yl [(size_t)TT * DD];

// ---------------- small helpers ------------------------------------------
__device__ __forceinline__ float silu_f(float x) { return x / (1.0f + __expf(-x)); }
__device__ __forceinline__ float softplus_f(float x) {
    return fmaxf(x, 0.0f) + log1pf(__expf(-fabsf(x)));
}
__device__ __forceinline__ uint32_t smem_u32(const void* p) {
    uint32_t a;
    asm("{ .reg .u64 t; cvta.to.shared.u64 t, %1; cvt.u32.u64 %0, t; }" : "=r"(a) : "l"(p));
    return a;
}
__device__ __forceinline__ unsigned short bf16_bits(__nv_bfloat16 h) {
    unsigned short u; *(__nv_bfloat16*)&u = h; return u;
}
__device__ __forceinline__ void split1(float v, unsigned short& h, unsigned short& l) {
    __nv_bfloat16 hb = __float2bfloat16(v);
    __nv_bfloat16 lb = __float2bfloat16(v - __bfloat162float(hb));
    h = bf16_bits(hb); l = bf16_bits(lb);
}
__device__ __forceinline__ void cp_async16(uint32_t dst, const void* src) {
    asm volatile("cp.async.cg.shared.global [%0], [%1], 16;" :: "r"(dst), "l"(src));
}
__device__ __forceinline__ void ldsm_x4(uint32_t addr, uint32_t& r0, uint32_t& r1,
                                        uint32_t& r2, uint32_t& r3) {
    asm volatile("ldmatrix.sync.aligned.m8n8.x4.shared.b16 {%0,%1,%2,%3}, [%4];"
                 : "=r"(r0), "=r"(r1), "=r"(r2), "=r"(r3) : "r"(addr));
}
__device__ __forceinline__ void mma_bf16(float* c, const uint32_t* a,
                                         uint32_t b0, uint32_t b1) {
    asm volatile(
        "mma.sync.aligned.m16n8k16.row.col.f32.bf16.bf16.f32 "
        "{%0,%1,%2,%3}, {%4,%5,%6,%7}, {%8,%9}, {%0,%1,%2,%3};"
        : "+f"(c[0]), "+f"(c[1]), "+f"(c[2]), "+f"(c[3])
        : "r"(a[0]), "r"(a[1]), "r"(a[2]), "r"(a[3]), "r"(b0), "r"(b1));
}

// ---------------- mma.sync split-bf16 GEMM, 256x128 tile ------------------
// C[M,N] = A @ B^T. A ~ Ah+Al ([M][ldk] bf16), B rows Bh/Bl [N][ldk] bf16.
// BK=64 (128B rows), 2-stage cp.async, 256 threads, warp tile 64x64.
// Split-K: blockIdx.z selects K-slice; partial written to C + z*M*N.
// EPI: 0 plain, 1 = +bias then softplus
#define G_AT 32768                   // A tile bytes: 256 x 128B
#define G_BT 16384                   // B tile bytes: 128 x 128B
#define G_STAGE (2*G_AT + 2*G_BT)    // 96KB
#define G_SMEM (2*G_STAGE + 1024)

template<int EPI>
__global__ __launch_bounds__(256, 1)
void mma_gemm256(const __nv_bfloat16* __restrict__ Ah, const __nv_bfloat16* __restrict__ Al,
                 const __nv_bfloat16* __restrict__ Bh, const __nv_bfloat16* __restrict__ Bl,
                 float* __restrict__ C, int M, int N, int ldk,
                 int kLen, const float* __restrict__ bias)
{
    extern __shared__ char smem_raw[];
    const uint32_t sb = (smem_u32(smem_raw) + 1023u) & ~1023u;

    const int tid  = threadIdx.x;
    const int lane = tid & 31;
    const int wid  = tid >> 5;
    const int wm   = wid & 3;        // 4 m-slabs of 64
    const int wn   = wid >> 2;       // 2 n-slabs of 64
    const int bm = blockIdx.y * 256;
    const int bn = blockIdx.x * 128;
    const int kOff = blockIdx.z * kLen;     // split-K offset (elements)
    C += (size_t)blockIdx.z * (size_t)M * (size_t)N;   // split-K partial plane

    // cp.async per-thread chunk offsets
    uint32_t swA[8]; size_t gA[8];           // A tiles: 2048 chunks -> 8/thread
    #pragma unroll
    for (int i = 0; i < 8; i++) {
        int c = i * 256 + tid;
        int row = c >> 3, kb = c & 7;
        uint32_t o = (uint32_t)(row * 128 + kb * 16);
        swA[i] = o ^ ((o >> 3) & 0x70);
        gA[i]  = (size_t)row * (size_t)ldk * 2 + (size_t)kb * 16;
    }
    uint32_t swB[4]; size_t gB[4];           // B tiles: 1024 chunks -> 4/thread
    #pragma unroll
    for (int i = 0; i < 4; i++) {
        int c = i * 256 + tid;
        int row = c >> 3, kb = c & 7;
        uint32_t o = (uint32_t)(row * 128 + kb * 16);
        swB[i] = o ^ ((o >> 3) & 0x70);
        gB[i]  = (size_t)row * (size_t)ldk * 2 + (size_t)kb * 16;
    }
    const char* srcAh = (const char*)(Ah + (size_t)bm * ldk + kOff);
    const char* srcAl = (const char*)(Al + (size_t)bm * ldk + kOff);
    const char* srcBh = (const char*)(Bh + (size_t)bn * ldk + kOff);
    const char* srcBl = (const char*)(Bl + (size_t)bn * ldk + kOff);

    float acc[4][8][4];
    #pragma unroll
    for (int mi = 0; mi < 4; mi++)
        #pragma unroll
        for (int ni = 0; ni < 8; ni++)
            #pragma unroll
            for (int r = 0; r < 4; r++) acc[mi][ni][r] = 0.0f;

    const int NK = kLen >> 6;

    auto load_stage = [&](int kblk, int s) {
        uint32_t base = sb + (uint32_t)s * G_STAGE;
        size_t kadd = (size_t)kblk * 128;
        #pragma unroll
        for (int i = 0; i < 8; i++) cp_async16(base + swA[i],           srcAh + kadd + gA[i]);
        #pragma unroll
        for (int i = 0; i < 8; i++) cp_async16(base + G_AT + swA[i],    srcAl + kadd + gA[i]);
        #pragma unroll
        for (int i = 0; i < 4; i++) cp_async16(base + 2*G_AT + swB[i],  srcBh + kadd + gB[i]);
        #pragma unroll
        for (int i = 0; i < 4; i++) cp_async16(base + 2*G_AT + G_BT + swB[i], srcBl + kadd + gB[i]);
        asm volatile("cp.async.commit_group;" ::: "memory");
    };

    load_stage(0, 0);

    for (int kblk = 0; kblk < NK; kblk++) {
        int s = kblk & 1;
        if (kblk + 1 < NK) {
            load_stage(kblk + 1, 1 - s);
            asm volatile("cp.async.wait_group 1;" ::: "memory");
        } else {
            asm volatile("cp.async.wait_group 0;" ::: "memory");
        }
        __syncthreads();

        uint32_t base = sb + (uint32_t)s * G_STAGE;
        uint32_t tAh = base, tAl = base + G_AT;
        uint32_t tBh = base + 2*G_AT, tBl = base + 2*G_AT + G_BT;

        #pragma unroll
        for (int kk = 0; kk < 4; kk++) {
            const int kb = kk * 32;
            // ldmatrix address pieces
            uint32_t aoff[4], boff[4];
            #pragma unroll
            for (int mi = 0; mi < 4; mi++) {
                int mrow = wm * 64 + mi * 16 + (lane & 15);
                int ko   = kb + ((lane >> 4) << 4);
                uint32_t o = (uint32_t)(mrow * 128 + ko);
                aoff[mi] = o ^ ((o >> 3) & 0x70);
            }
            #pragma unroll
            for (int nj = 0; nj < 4; nj++) {
                int nrow = wn * 64 + nj * 16 + (lane & 7) + ((lane >> 4) << 3);
                int ko   = kb + (((lane >> 3) & 1) << 4);
                uint32_t o = (uint32_t)(nrow * 128 + ko);
                boff[nj] = o ^ ((o >> 3) & 0x70);
            }

            uint32_t ah[16], bb[16], tt[16];
            #pragma unroll
            for (int mi = 0; mi < 4; mi++)
                ldsm_x4(tAh + aoff[mi], ah[mi*4+0], ah[mi*4+1], ah[mi*4+2], ah[mi*4+3]);
            #pragma unroll
            for (int nj = 0; nj < 4; nj++)
                ldsm_x4(tBh + boff[nj], bb[nj*4+0], bb[nj*4+1], bb[nj*4+2], bb[nj*4+3]);
            // pass 0: ah * bh
            #pragma unroll
            for (int mi = 0; mi < 4; mi++)
                #pragma unroll
                for (int ni = 0; ni < 8; ni++)
                    mma_bf16(acc[mi][ni], &ah[mi*4], bb[ni*2], bb[ni*2+1]);
            // pass 1: al * bh
            #pragma unroll
            for (int mi = 0; mi < 4; mi++)
                ldsm_x4(tAl + aoff[mi], tt[mi*4+0], tt[mi*4+1], tt[mi*4+2], tt[mi*4+3]);
            #pragma unroll
            for (int mi = 0; mi < 4; mi++)
                #pragma unroll
                for (int ni = 0; ni < 8; ni++)
                    mma_bf16(acc[mi][ni], &tt[mi*4], bb[ni*2], bb[ni*2+1]);
            // pass 2: ah * bl (reuse tt for bl)
            #pragma unroll
            for (int nj = 0; nj < 4; nj++)
                ldsm_x4(tBl + boff[nj], tt[nj*4+0], tt[nj*4+1], tt[nj*4+2], tt[nj*4+3]);
            #pragma unroll
            for (int mi = 0; mi < 4; mi++)
                #pragma unroll
                for (int ni = 0; ni < 8; ni++)
                    mma_bf16(acc[mi][ni], &ah[mi*4], tt[ni*2], tt[ni*2+1]);
        }
        __syncthreads();
    }

    // -- epilogue --
    #pragma unroll
    for (int mi = 0; mi < 4; mi++) {
        #pragma unroll
        for (int ni = 0; ni < 8; ni++) {
            int row = bm + wm * 64 + mi * 16 + (lane >> 2);
            int col = bn + wn * 64 + ni * 8 + (lane & 3) * 2;
            float2 v0 = make_float2(acc[mi][ni][0], acc[mi][ni][1]);
            float2 v1 = make_float2(acc[mi][ni][2], acc[mi][ni][3]);
            if (EPI == 1) {
                float b0 = __ldg(bias + col), b1 = __ldg(bias + col + 1);
                v0.x = softplus_f(v0.x + b0); v0.y = softplus_f(v0.y + b1);
                v1.x = softplus_f(v1.x + b0); v1.y = softplus_f(v1.y + b1);
            }
            *(float2*)(C + (size_t)row * N + col)       = v0;
            *(float2*)(C + (size_t)(row + 8) * N + col) = v1;
        }
    }
}

// ---------------- prep kernels --------------------------------------------
__global__ __launch_bounds__(256)
void split_kernel(const float* __restrict__ in, __nv_bfloat16* __restrict__ hi,
                  __nv_bfloat16* __restrict__ lo, int n4)
{
    int i = blockIdx.x * 256 + threadIdx.x;
    if (i >= n4) return;
    float4 v = ((const float4*)in)[i];
    ushort4 h, l;
    split1(v.x, h.x, l.x); split1(v.y, h.y, l.y);
    split1(v.z, h.z, l.z); split1(v.w, h.w, l.w);
    ((ushort4*)hi)[i] = h;
    ((ushort4*)lo)[i] = l;
}

// in: [R][C] fp32 -> outH/L: [C][R] bf16  (R, C multiples of 32)
__global__ __launch_bounds__(256)
void trsplit_kernel(const float* __restrict__ in, __nv_bfloat16* __restrict__ oh,
                    __nv_bfloat16* __restrict__ ol, int R, int C)
{
    __shared__ float t[32][33];
    int c0 = blockIdx.x * 32, r0 = blockIdx.y * 32;
    int tx = threadIdx.x, ty = threadIdx.y;
    #pragma unroll
    for (int j = 0; j < 4; j++)
        t[ty + 8 * j][tx] = in[(size_t)(r0 + ty + 8 * j) * C + c0 + tx];
    __syncthreads();
    #pragma unroll
    for (int j = 0; j < 4; j++) {
        float v = t[tx][ty + 8 * j];
        unsigned short h, l; split1(v, h, l);
        size_t o = (size_t)(c0 + ty + 8 * j) * R + r0 + tx;
        *(unsigned short*)(oh + o) = h;
        *(unsigned short*)(ol + o) = l;
    }
}

// reduce split-K partials -> xdbl (padded) + fused dt_in bf16 split
__global__ __launch_bounds__(256)
void xdbl_reduce_kernel(const float* __restrict__ part, float* __restrict__ xdbl,
                        __nv_bfloat16* __restrict__ dih, __nv_bfloat16* __restrict__ dil)
{
    int i = blockIdx.x * 256 + threadIdx.x;   // over TT*XPAD/4
    if (i >= TT * (XPAD / 4)) return;
    float4 s = make_float4(0.f, 0.f, 0.f, 0.f);
    #pragma unroll
    for (int z = 0; z < NSPLITK; z++) {
        float4 v = ((const float4*)(part + (size_t)z * TT * XPAD))[i];
        s.x += v.x; s.y += v.y; s.z += v.z; s.w += v.w;
    }
    ((float4*)xdbl)[i] = s;
    int col = (i & (XPAD/4 - 1)) * 4;
    if (col < RR) {
        int row = i / (XPAD/4);
        ushort4 h, l;
        split1(s.x, h.x, l.x); split1(s.y, h.y, l.y);
        split1(s.z, h.z, l.z); split1(s.w, h.w, l.w);
        size_t o = ((size_t)row * RR + col) >> 2;
        ((ushort4*)dih)[o] = h;
        ((ushort4*)dil)[o] = l;
    }
}

// ---------------- depthwise conv3 + bias + SiLU (+ bf16 split out) --------
__global__ __launch_bounds__(256)
void conv_silu_kernel(const float* __restrict__ xz, const float* __restrict__ w,
                      const float* __restrict__ bias, float* __restrict__ xc,
                      __nv_bfloat16* __restrict__ xch, __nv_bfloat16* __restrict__ xcl)
{
    int i = blockIdx.x * blockDim.x + threadIdx.x;
    const int NW = TT * (DD/4);
    if (i >= NW) return;
    int c4 = i % (DD/4);
    int t  = i / (DD/4);
    int l  = t & (LL - 1);
    int c  = c4 * 4;

    const float* p = xz + (size_t)t * (2*DD) + c;
    float4 x0 = *(const float4*)p;
    float4 xm = (l > 0)      ? *(const float4*)(p - 2*DD) : make_float4(0,0,0,0);
    float4 xp = (l < LL - 1) ? *(const float4*)(p + 2*DD) : make_float4(0,0,0,0);

    float xmv[4] = {xm.x, xm.y, xm.z, xm.w};
    float x0v[4] = {x0.x, x0.y, x0.z, x0.w};
    float xpv[4] = {xp.x, xp.y, xp.z, xp.w};
    float out[4];
    #pragma unroll
    for (int j = 0; j < 4; j++) {
        int cc = c + j;
        float v = xmv[j]*w[cc*3+0] + x0v[j]*w[cc*3+1] + xpv[j]*w[cc*3+2] + bias[cc];
        out[j] = silu_f(v);
    }
    *(float4*)(xc + (size_t)t*DD + c) = make_float4(out[0], out[1], out[2], out[3]);
    ushort4 h, l4;
    split1(out[0], h.x, l4.x); split1(out[1], h.y, l4.y);
    split1(out[2], h.z, l4.z); split1(out[3], h.w, l4.w);
    size_t o = ((size_t)t*DD + c) >> 2;
    ((ushort4*)xch)[o] = h;
    ((ushort4*)xcl)[o] = l4;
}

// ---------------- selective scan ------------------------------------------
__global__ __launch_bounds__(128)
void scan_kernel(const float* __restrict__ xc, const float* __restrict__ dt,
                 const float* __restrict__ xdbl, const float* __restrict__ A_log,
                 float* __restrict__ y)
{
    int c = blockIdx.x * 128 + threadIdx.x;
    int b = blockIdx.y;

    float eps[SSTATE];
    #pragma unroll
    for (int s = 0; s < SSTATE; s++)
        eps[s] = (float)(s + 1) - expf(A_log[(size_t)c*SSTATE + s]);

    float h[SSTATE];
    #pragma unroll
    for (int s = 0; s < SSTATE; s++) h[s] = 0.0f;

    const size_t base = (size_t)b * LL * DD + c;
    const size_t xb   = (size_t)b * LL * XPAD + RR;

    float u   = xc[base];
    float dtv = dt[base];

    float4 cur[8], nxt[8];
    #pragma unroll
    for (int j = 0; j < 8; j++) cur[j] = *(const float4*)(xdbl + xb + j * 4);

    for (int l = 0; l < LL; l++) {
        float un = 0.0f, dtn = 0.0f;
        if (l + 1 < LL) {
            un  = xc[base + (size_t)(l+1)*DD];
            dtn = dt[base + (size_t)(l+1)*DD];
            const float* xd = xdbl + xb + (size_t)(l+1) * XPAD;
            #pragma unroll
            for (int j = 0; j < 8; j++) nxt[j] = *(const float4*)(xd + j * 4);
        }
        float Bv[SSTATE] = {cur[0].x,cur[0].y,cur[0].z,cur[0].w, cur[1].x,cur[1].y,cur[1].z,cur[1].w,
                            cur[2].x,cur[2].y,cur[2].z,cur[2].w, cur[3].x,cur[3].y,cur[3].z,cur[3].w};
        float Cv[SSTATE] = {cur[4].x,cur[4].y,cur[4].z,cur[4].w, cur[5].x,cur[5].y,cur[5].z,cur[5].w,
                            cur[6].x,cur[6].y,cur[6].z,cur[6].w, cur[7].x,cur[7].y,cur[7].z,cur[7].w};

        float p1  = __expf(-dtv);
        float p2  = p1*p1;
        float p4  = p2*p2;
        float p8  = p4*p4;
        float p16 = p8*p8;
        float du  = dtv * u;

        float y0 = 0.f, y1 = 0.f, y2 = 0.f, y3 = 0.f;
        #pragma unroll
        for (int s = 0; s < SSTATE; s++) {
            const int e = s + 1;
            float pw = 1.0f;
            if (e & 1)  pw *= p1;
            if (e & 2)  pw *= p2;
            if (e & 4)  pw *= p4;
            if (e & 8)  pw *= p8;
            if (e & 16) pw *= p16;
            float dA = pw * fmaf(eps[s], dtv, 1.0f);
            h[s] = fmaf(dA, h[s], du * Bv[s]);
            float t2 = h[s] * Cv[s];
            if      ((s & 3) == 0) y0 += t2;
            else if ((s & 3) == 1) y1 += t2;
            else if ((s & 3) == 2) y2 += t2;
            else                   y3 += t2;
        }
        y[base + (size_t)l*DD] = (y0 + y1) + (y2 + y3);
        u = un; dtv = dtn;
        #pragma unroll
        for (int j = 0; j < 8; j++) cur[j] = nxt[j];
    }
}

// ---------------- gated mix + split ---------------------------------------
__global__ __launch_bounds__(256)
void final_mix_kernel(const float* __restrict__ xz, const float* __restrict__ xc,
                      const float* __restrict__ D, const float* __restrict__ y,
                      __nv_bfloat16* __restrict__ yh, __nv_bfloat16* __restrict__ yl)
{
    int i = blockIdx.x * blockDim.x + threadIdx.x;
    const int NW = TT * (DD/4);
    if (i >= NW) return;
    int c4 = i % (DD/4);
    int t  = i / (DD/4);
    int c  = c4 * 4;

    float4 ys  = *(const float4*)(y  + (size_t)t*DD + c);
    float4 xcv = *(const float4*)(xc + (size_t)t*DD + c);
    float4 Dv  = *(const float4*)(D + c);
    float4 zv  = *(const float4*)(xz + (size_t)t*(2*DD) + DD + c);

    float o0 = fmaf(xcv.x, Dv.x, ys.x) * silu_f(zv.x);
    float o1 = fmaf(xcv.y, Dv.y, ys.y) * silu_f(zv.y);
    float o2 = fmaf(xcv.z, Dv.z, ys.z) * silu_f(zv.z);
    float o3 = fmaf(xcv.w, Dv.w, ys.w) * silu_f(zv.w);

    ushort4 h, l;
    split1(o0, h.x, l.x); split1(o1, h.y, l.y);
    split1(o2, h.z, l.z); split1(o3, h.w, l.w);
    size_t o = ((size_t)t*DD + c) >> 2;
    ((ushort4*)yh)[o] = h;
    ((ushort4*)yl)[o] = l;
}

// ---------------- launch ---------------------------------------------------
extern "C" void kernel_launch(void* const* d_in, const int* in_sizes, int n_in,
                              void* d_out, int out_size)
{
    const float* x      = (const float*)d_in[0];
    const float* W_in   = (const float*)d_in[1];
    const float* conv_w = (const float*)d_in[2];
    const float* conv_b = (const float*)d_in[3];
    const float* W_x    = (const float*)d_in[4];
    const float* W_dt   = (const float*)d_in[5];
    const float* b_dt   = (const float*)d_in[6];
    const float* A_log  = (const float*)d_in[7];
    const float* D      = (const float*)d_in[8];
    const float* W_out  = (const float*)d_in[9];
    float* out = (float*)d_out;

    float *xz, *xc, *xdbl, *xpart, *dtb, *y;
    __nv_bfloat16 *xh, *xl, *wih, *wil, *woh, *wol, *wdh, *wdl, *wxh, *wxl;
    __nv_bfloat16 *xch, *xcl, *dih, *dil, *yh, *yl;
    cudaGetSymbolAddress((void**)&xz,    g_xz);
    cudaGetSymbolAddress((void**)&xc,    g_xc);
    cudaGetSymbolAddress((void**)&xdbl,  g_xdbl);
    cudaGetSymbolAddress((void**)&xpart, g_xpart);
    cudaGetSymbolAddress((void**)&dtb,   g_dt);
    cudaGetSymbolAddress((void**)&y,     g_y);
    cudaGetSymbolAddress((void**)&xh,  g_xh);  cudaGetSymbolAddress((void**)&xl,  g_xl);
    cudaGetSymbolAddress((void**)&wih, g_wih); cudaGetSymbolAddress((void**)&wil, g_wil);
    cudaGetSymbolAddress((void**)&woh, g_woh); cudaGetSymbolAddress((void**)&wol, g_wol);
    cudaGetSymbolAddress((void**)&wdh, g_wdh); cudaGetSymbolAddress((void**)&wdl, g_wdl);
    cudaGetSymbolAddress((void**)&wxh, g_wxh); cudaGetSymbolAddress((void**)&wxl, g_wxl);
    cudaGetSymbolAddress((void**)&xch, g_xch); cudaGetSymbolAddress((void**)&xcl, g_xcl);
    cudaGetSymbolAddress((void**)&dih, g_dih); cudaGetSymbolAddress((void**)&dil, g_dil);
    cudaGetSymbolAddress((void**)&yh,  g_yh);  cudaGetSymbolAddress((void**)&yl,  g_yl);

    cudaFuncSetAttribute(mma_gemm256<0>, cudaFuncAttributeMaxDynamicSharedMemorySize, G_SMEM);
    cudaFuncSetAttribute(mma_gemm256<1>, cudaFuncAttributeMaxDynamicSharedMemorySize, G_SMEM);

    // prep: split activations / transpose+split weights
    split_kernel<<<(TT*HH/4 + 255)/256, 256>>>(x, xh, xl, TT*HH/4);
    trsplit_kernel<<<dim3(2*DD/32, HH/32), dim3(32,8)>>>(W_in,  wih, wil, HH,  2*DD);
    trsplit_kernel<<<dim3(HH/32,  DD/32),  dim3(32,8)>>>(W_out, woh, wol, DD,  HH);
    trsplit_kernel<<<dim3(DD/32,  RR/32),  dim3(32,8)>>>(W_dt,  wdh, wdl, RR,  DD);
    trsplit_kernel<<<dim3(XDBL_N/32, DD/32), dim3(32,8)>>>(W_x, wxh, wxl, DD, XDBL_N);

    // 1) xz = x @ W_in    (2048 x 8192, K=2048)
    mma_gemm256<0><<<dim3(2*DD/128, TT/256), 256, G_SMEM>>>(
        xh, xl, wih, wil, xz, TT, 2*DD, HH, HH, nullptr);

    // 2) depthwise conv3 + bias + silu -> xc (+ bf16 split)
    conv_silu_kernel<<<(TT*(DD/4) + 255)/256, 256>>>(xz, conv_w, conv_b, xc, xch, xcl);

    // 3) x_dbl = xc @ W_x  (2048 x 256pad, K=4096) split-K=8 -> partials -> reduce
    mma_gemm256<0><<<dim3(XPAD/128, TT/256, NSPLITK), 256, G_SMEM>>>(
        xch, xcl, wxh, wxl, xpart, TT, XPAD, DD, DD/NSPLITK, nullptr);
    xdbl_reduce_kernel<<<(TT*(XPAD/4) + 255)/256, 256>>>(xpart, xdbl, dih, dil);

    // 4) dt = softplus(dt_in @ W_dt + b_dt)  (2048 x 4096, K=128)
    mma_gemm256<1><<<dim3(DD/128, TT/256), 256, G_SMEM>>>(
        dih, dil, wdh, wdl, dtb, TT, DD, RR, RR, b_dt);

    // 5) selective scan -> y
    scan_kernel<<<dim3(DD/128, BBATCH), 128>>>(xc, dtb, xdbl, A_log, y);

    // 6) yh/yl = split((y + xc*D) * silu(z))
    final_mix_kernel<<<(TT*(DD/4) + 255)/256, 256>>>(xz, xc, D, y, yh, yl);

    // 7) out = y @ W_out   (2048 x 2048, K=4096)
    mma_gemm256<0><<<dim3(HH/128, TT/256), 256, G_SMEM>>>(
        yh, yl, woh, wol, out, TT, HH, DD, DD, nullptr);
}